// round 1
// baseline (speedup 1.0000x reference)
#include <cuda_runtime.h>

#define NQ      22500
#define EMBED   256
#define HEADS   8
#define LEVELS  4
#define POINTS  4
#define CAMS    6
#define HEAD_DIM 32
#define TOTHW   30825   // 23200 + 5800 + 1450 + 375

__constant__ int c_HW[4]    = {23200, 5800, 1450, 375};
__constant__ int c_start[4] = {0, 23200, 29000, 30450};
__constant__ int c_H[4]     = {116, 58, 29, 15};
__constant__ int c_W[4]     = {200, 100, 50, 25};

// ---- scratch (device globals; no allocation allowed) ----
__device__ float g_v[CAMS * TOTHW * EMBED];      // projected values, ~189 MB
__device__ float g_oa[NQ * 384];                 // [off(256) | attn logits(128)] per query
__device__ float g_attn[NQ * 128];               // softmaxed attention weights
__device__ float g_ref2d[CAMS * NQ * 2];
__device__ unsigned char g_mask[CAMS * NQ];
__device__ float g_pre[NQ * EMBED];              // masked-summed pre-output
__device__ float g_valid[NQ];
__device__ float g_Wcat[EMBED * 384];            // [Wo | Wa]
__device__ float g_bcat[384];                    // [bo | ba]

// ============================================================
// prep: concat Wo|Wa and bo|ba
// ============================================================
__global__ void prep_wcat(const float* __restrict__ Wo, const float* __restrict__ Wa,
                          const float* __restrict__ bo, const float* __restrict__ ba) {
    int i = blockIdx.x * blockDim.x + threadIdx.x;
    if (i < 256 * 384) {
        int k = i / 384, n = i % 384;
        g_Wcat[i] = (n < 256) ? Wo[k * 256 + n] : Wa[k * 128 + (n - 256)];
    }
    if (i < 384) g_bcat[i] = (i < 256) ? bo[i] : ba[i - 256];
}

// ============================================================
// point sampling: project reference points into each camera
// ============================================================
__global__ void point_sample(const float* __restrict__ l2i, const float* __restrict__ refp,
                             const int* __restrict__ p_imgh, const int* __restrict__ p_imgw) {
    int t = blockIdx.x * blockDim.x + threadIdx.x;
    if (t >= CAMS * NQ) return;
    int cam = t / NQ, q = t - cam * NQ;
    float x = refp[q * 3 + 0], y = refp[q * 3 + 1], z = refp[q * 3 + 2];
    const float* M = l2i + cam * 16;
    float c0 = M[0] * x + M[1] * y + M[2]  * z + M[3];
    float c1 = M[4] * x + M[5] * y + M[6]  * z + M[7];
    float d  = M[8] * x + M[9] * y + M[10] * z + M[11];
    float eps = 1e-5f;
    float u = c0 / (d + eps);
    float v = c1 / (d + eps);
    float un = u / (float)p_imgw[0];
    float vn = v / (float)p_imgh[0];
    bool mk = (d > eps) && (un > 0.f) && (un < 1.f) && (vn > 0.f) && (vn < 1.f);
    g_ref2d[(size_t)(cam * NQ + q) * 2 + 0] = un;
    g_ref2d[(size_t)(cam * NQ + q) * 2 + 1] = vn;
    g_mask[cam * NQ + q] = mk ? 1 : 0;
}

// ============================================================
// GEMM 1: value projection.  v[cam, pix, :] = feat[cam, :, pix]^T @ Wv + bv
// A is K-major (channel-major feats) -> naturally coalesced tile loads.
// 128x128 blocktile, BK=8, 8x8 per thread, 256 threads.
// ============================================================
__global__ __launch_bounds__(256) void gemm_value(
        const float* __restrict__ f0, const float* __restrict__ f1,
        const float* __restrict__ f2, const float* __restrict__ f3,
        const float* __restrict__ Wv, const float* __restrict__ bv) {
    __shared__ float As[8][128];
    __shared__ float Bs[8][128];
    int seg = blockIdx.y;
    int cam = seg >> 2, lvl = seg & 3;
    int HW = c_HW[lvl];
    int m0 = blockIdx.x * 128;
    if (m0 >= HW) return;
    const float* feat = (lvl == 0 ? f0 : lvl == 1 ? f1 : lvl == 2 ? f2 : f3)
                        + (size_t)cam * EMBED * HW;
    float* vout = g_v + ((size_t)cam * TOTHW + c_start[lvl]) * EMBED;
    int n0 = blockIdx.z * 128;
    int tid = threadIdx.x;
    int ty = tid >> 4, tx = tid & 15;
    int kb = tid >> 5, cb = (tid & 31) * 4;
    float acc[8][8] = {};
    for (int k0 = 0; k0 < 256; k0 += 8) {
        #pragma unroll
        for (int i = 0; i < 4; i++) {
            int lin = tid + i * 256;
            int k = lin >> 7, m = lin & 127;
            As[k][m] = (m0 + m < HW) ? feat[(size_t)(k0 + k) * HW + m0 + m] : 0.f;
        }
        *(float4*)&Bs[kb][cb] = *(const float4*)(Wv + (size_t)(k0 + kb) * 256 + n0 + cb);
        __syncthreads();
        #pragma unroll
        for (int k = 0; k < 8; k++) {
            float ra[8], rb[8];
            #pragma unroll
            for (int i = 0; i < 8; i++) ra[i] = As[k][ty * 8 + i];
            #pragma unroll
            for (int j = 0; j < 8; j++) rb[j] = Bs[k][tx * 8 + j];
            #pragma unroll
            for (int i = 0; i < 8; i++)
                #pragma unroll
                for (int j = 0; j < 8; j++)
                    acc[i][j] += ra[i] * rb[j];
        }
        __syncthreads();
    }
    #pragma unroll
    for (int i = 0; i < 8; i++) {
        int m = m0 + ty * 8 + i;
        if (m < HW) {
            #pragma unroll
            for (int j = 0; j < 8; j++) {
                int n = n0 + tx * 8 + j;
                vout[(size_t)m * 256 + n] = acc[i][j] + bv[n];
            }
        }
    }
}

// ============================================================
// GEMM 2: q projection.  oa = (query+query_pos) @ [Wo|Wa] + [bo|ba]
// ============================================================
__global__ __launch_bounds__(256) void gemm_qproj(
        const float* __restrict__ query, const float* __restrict__ qpos) {
    __shared__ float As[8][128];
    __shared__ float Bs[8][128];
    int m0 = blockIdx.x * 128, n0 = blockIdx.y * 128;
    int tid = threadIdx.x;
    int ty = tid >> 4, tx = tid & 15;
    int aRow = tid >> 1, aCol = (tid & 1) * 4;
    int kb = tid >> 5, cb = (tid & 31) * 4;
    float acc[8][8] = {};
    for (int k0 = 0; k0 < 256; k0 += 8) {
        float4 av = make_float4(0.f, 0.f, 0.f, 0.f);
        int row = m0 + aRow;
        if (row < NQ) {
            float4 a1 = *(const float4*)(query + (size_t)row * 256 + k0 + aCol);
            float4 a2 = *(const float4*)(qpos  + (size_t)row * 256 + k0 + aCol);
            av = make_float4(a1.x + a2.x, a1.y + a2.y, a1.z + a2.z, a1.w + a2.w);
        }
        As[aCol + 0][aRow] = av.x;
        As[aCol + 1][aRow] = av.y;
        As[aCol + 2][aRow] = av.z;
        As[aCol + 3][aRow] = av.w;
        *(float4*)&Bs[kb][cb] = *(const float4*)(g_Wcat + (size_t)(k0 + kb) * 384 + n0 + cb);
        __syncthreads();
        #pragma unroll
        for (int k = 0; k < 8; k++) {
            float ra[8], rb[8];
            #pragma unroll
            for (int i = 0; i < 8; i++) ra[i] = As[k][ty * 8 + i];
            #pragma unroll
            for (int j = 0; j < 8; j++) rb[j] = Bs[k][tx * 8 + j];
            #pragma unroll
            for (int i = 0; i < 8; i++)
                #pragma unroll
                for (int j = 0; j < 8; j++)
                    acc[i][j] += ra[i] * rb[j];
        }
        __syncthreads();
    }
    #pragma unroll
    for (int i = 0; i < 8; i++) {
        int m = m0 + ty * 8 + i;
        if (m < NQ) {
            #pragma unroll
            for (int j = 0; j < 8; j++) {
                int n = n0 + tx * 8 + j;
                g_oa[(size_t)m * 384 + n] = acc[i][j] + g_bcat[n];
            }
        }
    }
}

// ============================================================
// softmax over the 16 (level,point) logits per (query, head)
// ============================================================
__global__ void softmax_attn() {
    int t = blockIdx.x * blockDim.x + threadIdx.x;
    if (t >= NQ * HEADS) return;
    int q = t >> 3, h = t & 7;
    const float* src = g_oa + (size_t)q * 384 + 256 + h * 16;
    float vals[16];
    float m = -1e30f;
    #pragma unroll
    for (int i = 0; i < 16; i++) { vals[i] = src[i]; m = fmaxf(m, vals[i]); }
    float s = 0.f;
    #pragma unroll
    for (int i = 0; i < 16; i++) { vals[i] = expf(vals[i] - m); s += vals[i]; }
    float* dst = g_attn + (size_t)q * 128 + h * 16;
    #pragma unroll
    for (int i = 0; i < 16; i++) dst[i] = vals[i] / s;
}

// ============================================================
// deformable sampling + masked accumulation over cameras.
// One warp per query; lane = head-dim channel (coalesced 128B gathers).
// ============================================================
__global__ __launch_bounds__(128) void sample_agg() {
    int gw = (blockIdx.x * blockDim.x + threadIdx.x) >> 5;
    int lane = threadIdx.x & 31;
    if (gw >= NQ) return;
    int q = gw;
    float acc[HEADS];
    #pragma unroll
    for (int h = 0; h < HEADS; h++) acc[h] = 0.f;
    float validf = 0.f;
    const float* offq = g_oa + (size_t)q * 384;
    const float* attq = g_attn + (size_t)q * 128;
    for (int cam = 0; cam < CAMS; cam++) {
        if (!g_mask[cam * NQ + q]) continue;
        validf += 1.f;
        float rx = g_ref2d[(size_t)(cam * NQ + q) * 2 + 0];
        float ry = g_ref2d[(size_t)(cam * NQ + q) * 2 + 1];
        const float* vcam = g_v + (size_t)cam * TOTHW * EMBED;
        #pragma unroll
        for (int l = 0; l < LEVELS; l++) {
            int W = c_W[l], H = c_H[l];
            const float* vl = vcam + (size_t)c_start[l] * EMBED;
            float bx = rx * (float)W - 0.5f;
            float by = ry * (float)H - 0.5f;
            #pragma unroll
            for (int h = 0; h < HEADS; h++) {
                const float* vlh = vl + h * HEAD_DIM + lane;
                #pragma unroll
                for (int p = 0; p < POINTS; p++) {
                    int oi = ((h * LEVELS + l) * POINTS + p) * 2;
                    float x = bx + offq[oi];
                    float y = by + offq[oi + 1];
                    float aw = attq[h * 16 + l * 4 + p];
                    float xf = floorf(x), yf = floorf(y);
                    int x0 = (int)xf, y0 = (int)yf;
                    float wx = x - xf, wy = y - yf;
                    bool xin0 = (x0 >= 0) && (x0 < W);
                    bool xin1 = (x0 + 1 >= 0) && (x0 + 1 < W);
                    float s = 0.f;
                    if (y0 >= 0 && y0 < H) {
                        const float* r = vlh + (size_t)y0 * W * EMBED;
                        if (xin0) s += (1.f - wx) * (1.f - wy) * r[(size_t)x0 * EMBED];
                        if (xin1) s += wx * (1.f - wy) * r[(size_t)(x0 + 1) * EMBED];
                    }
                    if (y0 + 1 >= 0 && y0 + 1 < H) {
                        const float* r = vlh + (size_t)(y0 + 1) * W * EMBED;
                        if (xin0) s += (1.f - wx) * wy * r[(size_t)x0 * EMBED];
                        if (xin1) s += wx * wy * r[(size_t)(x0 + 1) * EMBED];
                    }
                    acc[h] += aw * s;
                }
            }
        }
    }
    #pragma unroll
    for (int h = 0; h < HEADS; h++)
        g_pre[(size_t)q * EMBED + h * HEAD_DIM + lane] = acc[h];
    if (lane == 0) g_valid[q] = validf;
}

// ============================================================
// GEMM 3: output projection with fused bias*valid and /max(valid,1)
// ============================================================
__global__ __launch_bounds__(256) void gemm_out(
        const float* __restrict__ Wout, const float* __restrict__ bout,
        float* __restrict__ out) {
    __shared__ float As[8][128];
    __shared__ float Bs[8][128];
    int m0 = blockIdx.x * 128, n0 = blockIdx.y * 128;
    int tid = threadIdx.x;
    int ty = tid >> 4, tx = tid & 15;
    int aRow = tid >> 1, aCol = (tid & 1) * 4;
    int kb = tid >> 5, cb = (tid & 31) * 4;
    float acc[8][8] = {};
    for (int k0 = 0; k0 < 256; k0 += 8) {
        float4 av = make_float4(0.f, 0.f, 0.f, 0.f);
        int row = m0 + aRow;
        if (row < NQ)
            av = *(const float4*)(g_pre + (size_t)row * 256 + k0 + aCol);
        As[aCol + 0][aRow] = av.x;
        As[aCol + 1][aRow] = av.y;
        As[aCol + 2][aRow] = av.z;
        As[aCol + 3][aRow] = av.w;
        *(float4*)&Bs[kb][cb] = *(const float4*)(Wout + (size_t)(k0 + kb) * 256 + n0 + cb);
        __syncthreads();
        #pragma unroll
        for (int k = 0; k < 8; k++) {
            float ra[8], rb[8];
            #pragma unroll
            for (int i = 0; i < 8; i++) ra[i] = As[k][ty * 8 + i];
            #pragma unroll
            for (int j = 0; j < 8; j++) rb[j] = Bs[k][tx * 8 + j];
            #pragma unroll
            for (int i = 0; i < 8; i++)
                #pragma unroll
                for (int j = 0; j < 8; j++)
                    acc[i][j] += ra[i] * rb[j];
        }
        __syncthreads();
    }
    #pragma unroll
    for (int i = 0; i < 8; i++) {
        int m = m0 + ty * 8 + i;
        if (m < NQ) {
            float val = g_valid[m];
            float den = fmaxf(val, 1.f);
            #pragma unroll
            for (int j = 0; j < 8; j++) {
                int n = n0 + tx * 8 + j;
                out[(size_t)m * 256 + n] = (acc[i][j] + bout[n] * val) / den;
            }
        }
    }
}

// ============================================================
// launch
// ============================================================
extern "C" void kernel_launch(void* const* d_in, const int* in_sizes, int n_in,
                              void* d_out, int out_size) {
    const float *query = nullptr, *qpos = nullptr, *l2i = nullptr, *refp = nullptr;
    const float *f0 = nullptr, *f1 = nullptr, *f2 = nullptr, *f3 = nullptr;
    const float *Wv = nullptr, *Wo = nullptr, *Wout = nullptr, *Wa = nullptr;
    const float *bv = nullptr, *bo = nullptr, *bout = nullptr, *ba = nullptr;
    const int *ih = nullptr, *iw = nullptr;

    for (int i = 0; i < n_in; i++) {
        int s = in_sizes[i];
        const void* p = d_in[i];
        if (s == 5760000)       { if (!query) query = (const float*)p; else qpos = (const float*)p; }
        else if (s == 96)       { l2i  = (const float*)p; }
        else if (s == 67500)    { refp = (const float*)p; }
        else if (s == 35635200) { f0 = (const float*)p; }
        else if (s == 8908800)  { f1 = (const float*)p; }
        else if (s == 2227200)  { f2 = (const float*)p; }
        else if (s == 576000)   { f3 = (const float*)p; }
        else if (s == 65536)    { if (!Wv) Wv = (const float*)p; else if (!Wo) Wo = (const float*)p; else Wout = (const float*)p; }
        else if (s == 256)      { if (!bv) bv = (const float*)p; else if (!bo) bo = (const float*)p; else bout = (const float*)p; }
        else if (s == 32768)    { Wa = (const float*)p; }
        else if (s == 128)      { ba = (const float*)p; }
        else if (s == 1)        { if (!ih) ih = (const int*)p; else iw = (const int*)p; }
    }

    prep_wcat<<<(256 * 384 + 255) / 256, 256>>>(Wo, Wa, bo, ba);
    point_sample<<<(CAMS * NQ + 255) / 256, 256>>>(l2i, refp, ih, iw);
    gemm_value<<<dim3(182, 24, 2), 256>>>(f0, f1, f2, f3, Wv, bv);
    gemm_qproj<<<dim3((NQ + 127) / 128, 3), 256>>>(query, qpos);
    softmax_attn<<<(NQ * HEADS + 255) / 256, 256>>>();
    sample_agg<<<(NQ * 32 + 127) / 128, 128>>>();
    gemm_out<<<dim3((NQ + 127) / 128, 2), 256>>>(Wout, bout, (float*)d_out);
}

// round 4
// speedup vs baseline: 1.2478x; 1.2478x over previous
#include <cuda_runtime.h>
#include <mma.h>

using namespace nvcuda;

#define NQ      22500
#define NQP     22528            // padded to 128
#define EMBED   256
#define HEADS   8
#define LEVELS  4
#define POINTS  4
#define CAMS    6
#define HEAD_DIM 32
#define TOTHWP  31104            // padded: 23296 + 5888 + 1536 + 384

__constant__ int c_HW[4]     = {23200, 5800, 1450, 375};
__constant__ int c_startp[4] = {0, 23296, 29184, 30720};
__constant__ int c_H[4]      = {116, 58, 29, 15};
__constant__ int c_W[4]      = {200, 100, 50, 25};

// ---- scratch (device globals; no allocation allowed) ----
__device__ float g_v[CAMS * TOTHWP * EMBED];     // projected values (padded), ~191 MB
__device__ float g_oa[NQP * 384];                // [off(256) | attn logits(128)] per query (no bias)
__device__ float g_attn[NQ * 128];               // softmaxed attention weights
__device__ float g_ref2d[CAMS * NQ * 2];
__device__ unsigned char g_mask[CAMS * NQ];
__device__ float g_pre[NQP * EMBED];             // masked-summed pre-output (padded)
__device__ float g_valid[NQ];
__device__ float g_out[NQP * EMBED];             // out-proj result before finalize
__device__ float g_Wcat[EMBED * 384];            // [Wo | Wa]

// ============================================================
// prep: concat Wo|Wa
// ============================================================
__global__ void prep_wcat(const float* __restrict__ Wo, const float* __restrict__ Wa) {
    int i = blockIdx.x * blockDim.x + threadIdx.x;
    if (i < 256 * 384) {
        int k = i / 384, n = i % 384;
        g_Wcat[i] = (n < 256) ? Wo[k * 256 + n] : Wa[k * 128 + (n - 256)];
    }
}

// ============================================================
// point sampling
// ============================================================
__global__ void point_sample(const float* __restrict__ l2i, const float* __restrict__ refp,
                             const int* __restrict__ p_imgh, const int* __restrict__ p_imgw) {
    int t = blockIdx.x * blockDim.x + threadIdx.x;
    if (t >= CAMS * NQ) return;
    int cam = t / NQ, q = t - cam * NQ;
    float x = refp[q * 3 + 0], y = refp[q * 3 + 1], z = refp[q * 3 + 2];
    const float* M = l2i + cam * 16;
    float c0 = M[0] * x + M[1] * y + M[2]  * z + M[3];
    float c1 = M[4] * x + M[5] * y + M[6]  * z + M[7];
    float d  = M[8] * x + M[9] * y + M[10] * z + M[11];
    float eps = 1e-5f;
    float u = c0 / (d + eps);
    float v = c1 / (d + eps);
    float un = u / (float)p_imgw[0];
    float vn = v / (float)p_imgh[0];
    bool mk = (d > eps) && (un > 0.f) && (un < 1.f) && (vn > 0.f) && (vn < 1.f);
    g_ref2d[(size_t)(cam * NQ + q) * 2 + 0] = un;
    g_ref2d[(size_t)(cam * NQ + q) * 2 + 1] = vn;
    g_mask[cam * NQ + q] = mk ? 1 : 0;
}

// ============================================================
// GEMM 1 (tf32 wmma): value projection, A is K-major (native col-major)
// 128x128 block tile, BK=16, 8 warps of 32x64. No bias (folded downstream).
// ============================================================
__global__ __launch_bounds__(256) void gemm_value(
        const float* __restrict__ f0, const float* __restrict__ f1,
        const float* __restrict__ f2, const float* __restrict__ f3,
        const float* __restrict__ Wv) {
    __shared__ __align__(16) float As[16][132];   // [k][m] (col-major A)
    __shared__ __align__(16) float Bs[16][132];   // [k][n]
    int seg = blockIdx.y;
    int cam = seg >> 2, lvl = seg & 3;
    int HW = c_HW[lvl];
    int m0 = blockIdx.x * 128;
    if (m0 >= HW) return;
    const float* feat = (lvl == 0 ? f0 : lvl == 1 ? f1 : lvl == 2 ? f2 : f3)
                        + (size_t)cam * EMBED * HW;
    float* vout = g_v + ((size_t)cam * TOTHWP + c_startp[lvl]) * EMBED;
    int n0 = blockIdx.z * 128;
    int tid = threadIdx.x;
    int wid = tid >> 5;
    int wm = wid & 3, wn = wid >> 2;
    bool full = (m0 + 128 <= HW);

    wmma::fragment<wmma::accumulator, 16, 16, 8, float> acc[2][4];
    #pragma unroll
    for (int i = 0; i < 2; i++)
        #pragma unroll
        for (int j = 0; j < 4; j++)
            wmma::fill_fragment(acc[i][j], 0.f);

    for (int k0 = 0; k0 < 256; k0 += 16) {
        if (full) {
            #pragma unroll
            for (int i = 0; i < 8; i++) {
                int lin = tid + i * 256;
                int k = lin >> 7, m = lin & 127;
                As[k][m] = feat[(size_t)(k0 + k) * HW + m0 + m];
            }
        } else {
            #pragma unroll
            for (int i = 0; i < 8; i++) {
                int lin = tid + i * 256;
                int k = lin >> 7, m = lin & 127;
                As[k][m] = (m0 + m < HW) ? feat[(size_t)(k0 + k) * HW + m0 + m] : 0.f;
            }
        }
        #pragma unroll
        for (int i = 0; i < 2; i++) {
            int lin = tid + i * 256;
            int k = lin >> 5, n4 = (lin & 31) * 4;
            *(float4*)&Bs[k][n4] = *(const float4*)(Wv + (size_t)(k0 + k) * 256 + n0 + n4);
        }
        __syncthreads();
        #pragma unroll
        for (int kk = 0; kk < 16; kk += 8) {
            wmma::fragment<wmma::matrix_a, 16, 16, 8, wmma::precision::tf32, wmma::col_major> a[2];
            wmma::fragment<wmma::matrix_b, 16, 16, 8, wmma::precision::tf32, wmma::row_major> b[4];
            #pragma unroll
            for (int i = 0; i < 2; i++) {
                wmma::load_matrix_sync(a[i], &As[kk][wm * 32 + i * 16], 132);
                #pragma unroll
                for (int t = 0; t < a[i].num_elements; t++)
                    a[i].x[t] = wmma::__float_to_tf32(a[i].x[t]);
            }
            #pragma unroll
            for (int j = 0; j < 4; j++) {
                wmma::load_matrix_sync(b[j], &Bs[kk][wn * 64 + j * 16], 132);
                #pragma unroll
                for (int t = 0; t < b[j].num_elements; t++)
                    b[j].x[t] = wmma::__float_to_tf32(b[j].x[t]);
            }
            #pragma unroll
            for (int i = 0; i < 2; i++)
                #pragma unroll
                for (int j = 0; j < 4; j++)
                    wmma::mma_sync(acc[i][j], a[i], b[j], acc[i][j]);
        }
        __syncthreads();
    }
    #pragma unroll
    for (int i = 0; i < 2; i++)
        #pragma unroll
        for (int j = 0; j < 4; j++)
            wmma::store_matrix_sync(
                vout + (size_t)(m0 + wm * 32 + i * 16) * 256 + n0 + wn * 64 + j * 16,
                acc[i][j], 256, wmma::mem_row_major);
}

// ============================================================
// GEMM 2 (tf32 wmma): oa = (query+query_pos) @ [Wo|Wa]  (A row-major)
// ============================================================
__global__ __launch_bounds__(256) void gemm_qproj(
        const float* __restrict__ query, const float* __restrict__ qpos) {
    __shared__ __align__(16) float As[128][20];   // [m][k] row-major A
    __shared__ __align__(16) float Bs[16][132];   // [k][n]
    int m0 = blockIdx.x * 128, n0 = blockIdx.y * 128;
    int tid = threadIdx.x;
    int wid = tid >> 5;
    int wm = wid & 3, wn = wid >> 2;

    wmma::fragment<wmma::accumulator, 16, 16, 8, float> acc[2][4];
    #pragma unroll
    for (int i = 0; i < 2; i++)
        #pragma unroll
        for (int j = 0; j < 4; j++)
            wmma::fill_fragment(acc[i][j], 0.f);

    for (int k0 = 0; k0 < 256; k0 += 16) {
        #pragma unroll
        for (int it = 0; it < 2; it++) {
            int row = (tid >> 2) + it * 64;
            int k4 = (tid & 3) * 4;
            float4 av = make_float4(0.f, 0.f, 0.f, 0.f);
            if (m0 + row < NQ) {
                float4 a1 = *(const float4*)(query + (size_t)(m0 + row) * 256 + k0 + k4);
                float4 a2 = *(const float4*)(qpos  + (size_t)(m0 + row) * 256 + k0 + k4);
                av = make_float4(a1.x + a2.x, a1.y + a2.y, a1.z + a2.z, a1.w + a2.w);
            }
            *(float4*)&As[row][k4] = av;
        }
        #pragma unroll
        for (int i = 0; i < 2; i++) {
            int lin = tid + i * 256;
            int k = lin >> 5, n4 = (lin & 31) * 4;
            *(float4*)&Bs[k][n4] = *(const float4*)(g_Wcat + (size_t)(k0 + k) * 384 + n0 + n4);
        }
        __syncthreads();
        #pragma unroll
        for (int kk = 0; kk < 16; kk += 8) {
            wmma::fragment<wmma::matrix_a, 16, 16, 8, wmma::precision::tf32, wmma::row_major> a[2];
            wmma::fragment<wmma::matrix_b, 16, 16, 8, wmma::precision::tf32, wmma::row_major> b[4];
            #pragma unroll
            for (int i = 0; i < 2; i++) {
                wmma::load_matrix_sync(a[i], &As[wm * 32 + i * 16][kk], 20);
                #pragma unroll
                for (int t = 0; t < a[i].num_elements; t++)
                    a[i].x[t] = wmma::__float_to_tf32(a[i].x[t]);
            }
            #pragma unroll
            for (int j = 0; j < 4; j++) {
                wmma::load_matrix_sync(b[j], &Bs[kk][wn * 64 + j * 16], 132);
                #pragma unroll
                for (int t = 0; t < b[j].num_elements; t++)
                    b[j].x[t] = wmma::__float_to_tf32(b[j].x[t]);
            }
            #pragma unroll
            for (int i = 0; i < 2; i++)
                #pragma unroll
                for (int j = 0; j < 4; j++)
                    wmma::mma_sync(acc[i][j], a[i], b[j], acc[i][j]);
        }
        __syncthreads();
    }
    #pragma unroll
    for (int i = 0; i < 2; i++)
        #pragma unroll
        for (int j = 0; j < 4; j++)
            wmma::store_matrix_sync(
                g_oa + (size_t)(m0 + wm * 32 + i * 16) * 384 + n0 + wn * 64 + j * 16,
                acc[i][j], 384, wmma::mem_row_major);
}

// ============================================================
// softmax with ba folded in
// ============================================================
__global__ void softmax_attn(const float* __restrict__ ba) {
    int t = blockIdx.x * blockDim.x + threadIdx.x;
    if (t >= NQ * HEADS) return;
    int q = t >> 3, h = t & 7;
    const float* src = g_oa + (size_t)q * 384 + 256 + h * 16;
    const float* bah = ba + h * 16;
    float vals[16];
    float m = -1e30f;
    #pragma unroll
    for (int i = 0; i < 16; i++) { vals[i] = src[i] + bah[i]; m = fmaxf(m, vals[i]); }
    float s = 0.f;
    #pragma unroll
    for (int i = 0; i < 16; i++) { vals[i] = expf(vals[i] - m); s += vals[i]; }
    float* dst = g_attn + (size_t)q * 128 + h * 16;
    #pragma unroll
    for (int i = 0; i < 16; i++) dst[i] = vals[i] / s;
}

// ============================================================
// deformable sampling + masked accumulation (bv, bo folded in)
// One warp per query; lane = head-dim channel.
// ============================================================
__global__ __launch_bounds__(128) void sample_agg(const float* __restrict__ bv,
                                                  const float* __restrict__ bo) {
    int gw = (blockIdx.x * blockDim.x + threadIdx.x) >> 5;
    int lane = threadIdx.x & 31;
    if (gw >= NQ) return;
    int q = gw;
    float acc[HEADS];
    float bvh[HEADS];
    #pragma unroll
    for (int h = 0; h < HEADS; h++) { acc[h] = 0.f; bvh[h] = bv[h * HEAD_DIM + lane]; }
    float validf = 0.f;
    const float* offq = g_oa + (size_t)q * 384;
    const float* attq = g_attn + (size_t)q * 128;
    for (int cam = 0; cam < CAMS; cam++) {
        if (!g_mask[cam * NQ + q]) continue;
        validf += 1.f;
        float rx = g_ref2d[(size_t)(cam * NQ + q) * 2 + 0];
        float ry = g_ref2d[(size_t)(cam * NQ + q) * 2 + 1];
        const float* vcam = g_v + (size_t)cam * TOTHWP * EMBED;
        #pragma unroll
        for (int l = 0; l < LEVELS; l++) {
            int W = c_W[l], H = c_H[l];
            const float* vl = vcam + (size_t)c_startp[l] * EMBED;
            float bx = rx * (float)W - 0.5f;
            float by = ry * (float)H - 0.5f;
            #pragma unroll
            for (int h = 0; h < HEADS; h++) {
                const float* vlh = vl + h * HEAD_DIM + lane;
                #pragma unroll
                for (int p = 0; p < POINTS; p++) {
                    int oi = ((h * LEVELS + l) * POINTS + p) * 2;
                    float x = bx + offq[oi] + bo[oi];
                    float y = by + offq[oi + 1] + bo[oi + 1];
                    float aw = attq[h * 16 + l * 4 + p];
                    float xf = floorf(x), yf = floorf(y);
                    int x0 = (int)xf, y0 = (int)yf;
                    float wx = x - xf, wy = y - yf;
                    bool xin0 = (x0 >= 0) && (x0 < W);
                    bool xin1 = (x0 + 1 >= 0) && (x0 + 1 < W);
                    float s = 0.f;
                    float wsum = 0.f;
                    if (y0 >= 0 && y0 < H) {
                        const float* r = vlh + (size_t)y0 * W * EMBED;
                        if (xin0) { float w00 = (1.f - wx) * (1.f - wy); s += w00 * r[(size_t)x0 * EMBED]; wsum += w00; }
                        if (xin1) { float w10 = wx * (1.f - wy);         s += w10 * r[(size_t)(x0 + 1) * EMBED]; wsum += w10; }
                    }
                    if (y0 + 1 >= 0 && y0 + 1 < H) {
                        const float* r = vlh + (size_t)(y0 + 1) * W * EMBED;
                        if (xin0) { float w01 = (1.f - wx) * wy; s += w01 * r[(size_t)x0 * EMBED]; wsum += w01; }
                        if (xin1) { float w11 = wx * wy;         s += w11 * r[(size_t)(x0 + 1) * EMBED]; wsum += w11; }
                    }
                    acc[h] += aw * (s + bvh[h] * wsum);
                }
            }
        }
    }
    #pragma unroll
    for (int h = 0; h < HEADS; h++)
        g_pre[(size_t)q * EMBED + h * HEAD_DIM + lane] = acc[h];
    if (lane == 0) g_valid[q] = validf;
}

// ============================================================
// GEMM 3 (tf32 wmma): out = g_pre @ Wout  (bias/valid folded in finalize)
// ============================================================
__global__ __launch_bounds__(256) void gemm_out(const float* __restrict__ Wout) {
    __shared__ __align__(16) float As[128][20];
    __shared__ __align__(16) float Bs[16][132];
    int m0 = blockIdx.x * 128, n0 = blockIdx.y * 128;
    int tid = threadIdx.x;
    int wid = tid >> 5;
    int wm = wid & 3, wn = wid >> 2;

    wmma::fragment<wmma::accumulator, 16, 16, 8, float> acc[2][4];
    #pragma unroll
    for (int i = 0; i < 2; i++)
        #pragma unroll
        for (int j = 0; j < 4; j++)
            wmma::fill_fragment(acc[i][j], 0.f);

    for (int k0 = 0; k0 < 256; k0 += 16) {
        #pragma unroll
        for (int it = 0; it < 2; it++) {
            int row = (tid >> 2) + it * 64;
            int k4 = (tid & 3) * 4;
            *(float4*)&As[row][k4] =
                *(const float4*)(g_pre + (size_t)(m0 + row) * 256 + k0 + k4);
        }
        #pragma unroll
        for (int i = 0; i < 2; i++) {
            int lin = tid + i * 256;
            int k = lin >> 5, n4 = (lin & 31) * 4;
            *(float4*)&Bs[k][n4] = *(const float4*)(Wout + (size_t)(k0 + k) * 256 + n0 + n4);
        }
        __syncthreads();
        #pragma unroll
        for (int kk = 0; kk < 16; kk += 8) {
            wmma::fragment<wmma::matrix_a, 16, 16, 8, wmma::precision::tf32, wmma::row_major> a[2];
            wmma::fragment<wmma::matrix_b, 16, 16, 8, wmma::precision::tf32, wmma::row_major> b[4];
            #pragma unroll
            for (int i = 0; i < 2; i++) {
                wmma::load_matrix_sync(a[i], &As[wm * 32 + i * 16][kk], 20);
                #pragma unroll
                for (int t = 0; t < a[i].num_elements; t++)
                    a[i].x[t] = wmma::__float_to_tf32(a[i].x[t]);
            }
            #pragma unroll
            for (int j = 0; j < 4; j++) {
                wmma::load_matrix_sync(b[j], &Bs[kk][wn * 64 + j * 16], 132);
                #pragma unroll
                for (int t = 0; t < b[j].num_elements; t++)
                    b[j].x[t] = wmma::__float_to_tf32(b[j].x[t]);
            }
            #pragma unroll
            for (int i = 0; i < 2; i++)
                #pragma unroll
                for (int j = 0; j < 4; j++)
                    wmma::mma_sync(acc[i][j], a[i], b[j], acc[i][j]);
        }
        __syncthreads();
    }
    #pragma unroll
    for (int i = 0; i < 2; i++)
        #pragma unroll
        for (int j = 0; j < 4; j++)
            wmma::store_matrix_sync(
                g_out + (size_t)(m0 + wm * 32 + i * 16) * 256 + n0 + wn * 64 + j * 16,
                acc[i][j], 256, wmma::mem_row_major);
}

// ============================================================
// finalize: out = (g_out + bout*valid) / max(valid, 1)
// ============================================================
__global__ void finalize(const float* __restrict__ bout, float* __restrict__ out) {
    int t = blockIdx.x * blockDim.x + threadIdx.x;
    if (t >= NQ * 64) return;          // float4 granularity
    int m = t >> 6, n4 = (t & 63) * 4;
    float val = g_valid[m];
    float den = 1.f / fmaxf(val, 1.f);
    float4 v = *(const float4*)(g_out + (size_t)m * 256 + n4);
    float4 b = *(const float4*)(bout + n4);
    float4 r;
    r.x = (v.x + b.x * val) * den;
    r.y = (v.y + b.y * val) * den;
    r.z = (v.z + b.z * val) * den;
    r.w = (v.w + b.w * val) * den;
    *(float4*)(out + (size_t)m * 256 + n4) = r;
}

// ============================================================
// launch
// ============================================================
extern "C" void kernel_launch(void* const* d_in, const int* in_sizes, int n_in,
                              void* d_out, int out_size) {
    const float *query = nullptr, *qpos = nullptr, *l2i = nullptr, *refp = nullptr;
    const float *f0 = nullptr, *f1 = nullptr, *f2 = nullptr, *f3 = nullptr;
    const float *Wv = nullptr, *Wo = nullptr, *Wout = nullptr, *Wa = nullptr;
    const float *bv = nullptr, *bo = nullptr, *bout = nullptr, *ba = nullptr;
    const int *ih = nullptr, *iw = nullptr;

    for (int i = 0; i < n_in; i++) {
        int s = in_sizes[i];
        const void* p = d_in[i];
        if (s == 5760000)       { if (!query) query = (const float*)p; else qpos = (const float*)p; }
        else if (s == 96)       { l2i  = (const float*)p; }
        else if (s == 67500)    { refp = (const float*)p; }
        else if (s == 35635200) { f0 = (const float*)p; }
        else if (s == 8908800)  { f1 = (const float*)p; }
        else if (s == 2227200)  { f2 = (const float*)p; }
        else if (s == 576000)   { f3 = (const float*)p; }
        else if (s == 65536)    { if (!Wv) Wv = (const float*)p; else if (!Wo) Wo = (const float*)p; else Wout = (const float*)p; }
        else if (s == 256)      { if (!bv) bv = (const float*)p; else if (!bo) bo = (const float*)p; else bout = (const float*)p; }
        else if (s == 32768)    { Wa = (const float*)p; }
        else if (s == 128)      { ba = (const float*)p; }
        else if (s == 1)        { if (!ih) ih = (const int*)p; else iw = (const int*)p; }
    }

    prep_wcat<<<(256 * 384 + 255) / 256, 256>>>(Wo, Wa);
    point_sample<<<(CAMS * NQ + 255) / 256, 256>>>(l2i, refp, ih, iw);
    gemm_value<<<dim3(182, 24, 2), 256>>>(f0, f1, f2, f3, Wv);
    gemm_qproj<<<dim3(NQP / 128, 3), 256>>>(query, qpos);
    softmax_attn<<<(NQ * HEADS + 255) / 256, 256>>>(ba);
    sample_agg<<<(NQ * 32 + 127) / 128, 128>>>(bv, bo);
    gemm_out<<<dim3(NQP / 128, 2), 256>>>(Wout);
    finalize<<<(NQ * 64 + 255) / 256, 256>>>(bout, (float*)d_out);
}